// round 3
// baseline (speedup 1.0000x reference)
#include <cuda_runtime.h>
#include <cstdint>

#define CAP        500000
#define FDIM       128
#define BATCH      256
#define KNEG       4096
#define ROWS_PER_B (KNEG + 1)   // 4097
#define NCHUNK     8
#define CHUNK_ROWS ((CAP + NCHUNK - 1) / NCHUNK)   // 62500

// Scratch state (allocation-free). g_pos is zero-initialized at module load;
// every launch restores it to all-zeros (scatter then cleanup), so replays
// are deterministic. Encoding: 0 = row not updated, else (batch_pos + 1).
__device__ int   g_pos[CAP];
__device__ float g_upd_s[BATCH * FDIM];
__device__ float g_upd_t[BATCH * FDIM];

// One block per (which, batch-row): EMA + L2 normalize into scratch.
__global__ void cm_update_kernel(const float* __restrict__ f_s,
                                 const float* __restrict__ f_t,
                                 const float* __restrict__ mem1,
                                 const float* __restrict__ mem2,
                                 const int*   __restrict__ s_layer_p,
                                 const int*   __restrict__ t_layer_p,
                                 const int*   __restrict__ idx)
{
    const int i     = blockIdx.x & (BATCH - 1);
    const int which = blockIdx.x >> 8;          // 0 = s, 1 = t
    const int t     = threadIdx.x;              // 0..127

    const float* f    = which ? f_t : f_s;
    const float* mem  = which ? mem2 : mem1;
    const int layer   = which ? *t_layer_p : *s_layer_p;
    const int row     = idx[i];

    const float oldv = mem[(size_t)layer * CAP * FDIM + (size_t)row * FDIM + t];
    const float v    = 0.5f * oldv + 0.5f * f[i * FDIM + t];

    float s = v * v;
    #pragma unroll
    for (int o = 16; o; o >>= 1) s += __shfl_xor_sync(0xffffffffu, s, o);
    __shared__ float ws[4];
    if ((t & 31) == 0) ws[t >> 5] = s;
    __syncthreads();
    const float tot = ws[0] + ws[1] + ws[2] + ws[3];

    const float outv = v / sqrtf(tot);
    (which ? g_upd_t : g_upd_s)[i * FDIM + t] = outv;

    if (t == 0 && which == 0) g_pos[row] = i + 1;  // publish updated-row map
}

// L2 evict-last load of a float4 (keeps chunk rows resident in L2).
__device__ __forceinline__ float4 ld_evict_last(const float4* p, uint64_t pol)
{
    float4 v;
    asm volatile("ld.global.L2::cache_hint.v4.f32 {%0,%1,%2,%3}, [%4], %5;"
                 : "=f"(v.x), "=f"(v.y), "=f"(v.z), "=f"(v.w)
                 : "l"(p), "l"(pol));
    return v;
}

// Chunked gather pass. Grid: x = j-tiles (8 warps/block), y = b, z = which.
// A warp handles one output row; it only does the copy if src falls in
// [chunk_lo, chunk_hi), so each pass's read working set (<=64MB across both
// tensors) stays L2-resident and row reuse becomes L2 hits.
__global__ void cm_gather_pass_kernel(const float* __restrict__ mem1,
                                      const float* __restrict__ mem2,
                                      const int*   __restrict__ s_layer_p,
                                      const int*   __restrict__ t_layer_p,
                                      const int*   __restrict__ idx,
                                      const int*   __restrict__ cidx,
                                      float*       __restrict__ out,
                                      int chunk_lo, int chunk_hi)
{
    const int warp = threadIdx.x >> 5;
    const int lane = threadIdx.x & 31;
    const int j    = blockIdx.x * 8 + warp;        // 0..4103
    if (j >= ROWS_PER_B) return;
    const int b     = blockIdx.y;
    const int which = blockIdx.z;

    const int src = (j == 0) ? idx[b] : cidx[b * KNEG + (j - 1)];
    if (src < chunk_lo || src >= chunk_hi) return;

    uint64_t pol;
    asm("createpolicy.fractional.L2::evict_last.b64 %0, 1.0;" : "=l"(pol));

    const int p = g_pos[src];
    float4 v;
    if (p > 0) {
        const float* upd = which ? g_upd_t : g_upd_s;
        v = ((const float4*)(upd + (size_t)(p - 1) * FDIM))[lane];
    } else {
        const float* mem   = which ? mem2 : mem1;
        const int    layer = which ? *t_layer_p : *s_layer_p;
        v = ld_evict_last((const float4*)(mem + (size_t)layer * CAP * FDIM
                                              + (size_t)src * FDIM) + lane, pol);
    }

    // out row index: which * B*R + b * R + j
    float4* op = (float4*)(out + (((size_t)which * BATCH + b) * ROWS_PER_B + j)
                                 * (size_t)FDIM);
    __stcs(op + lane, v);
}

// Restore g_pos to all-zeros for the next (graph-replayed) launch.
__global__ void cm_cleanup_kernel(const int* __restrict__ idx)
{
    g_pos[idx[threadIdx.x]] = 0;
}

extern "C" void kernel_launch(void* const* d_in, const int* in_sizes, int n_in,
                              void* d_out, int out_size)
{
    const float* f_s      = (const float*)d_in[0];
    const float* f_t      = (const float*)d_in[1];
    const float* mem1     = (const float*)d_in[2];
    const float* mem2     = (const float*)d_in[3];
    const int*   s_layer  = (const int*)  d_in[4];
    const int*   t_layer  = (const int*)  d_in[5];
    const int*   idx      = (const int*)  d_in[6];
    const int*   cidx     = (const int*)  d_in[7];
    float*       out      = (float*)d_out;

    cm_update_kernel<<<2 * BATCH, FDIM>>>(f_s, f_t, mem1, mem2, s_layer, t_layer, idx);

    dim3 grid((ROWS_PER_B + 7) / 8, BATCH, 2);   // 513 x 256 x 2, 8 warps/block
    for (int c = 0; c < NCHUNK; c++) {
        const int lo = c * CHUNK_ROWS;
        const int hi = (c == NCHUNK - 1) ? CAP : lo + CHUNK_ROWS;
        cm_gather_pass_kernel<<<grid, 256>>>(mem1, mem2, s_layer, t_layer,
                                             idx, cidx, out, lo, hi);
    }

    cm_cleanup_kernel<<<1, BATCH>>>(idx);
}

// round 4
// speedup vs baseline: 4.3090x; 4.3090x over previous
#include <cuda_runtime.h>
#include <cstdint>

#define CAP        500000
#define FDIM       128
#define BATCH      256
#define KNEG       4096
#define ROWS_PER_B (KNEG + 1)     // 4097
#define NCHUNK     8
#define CHUNK_ROWS 62500          // ceil(CAP / NCHUNK)
#define ENT_TOTAL  (BATCH * ROWS_PER_B)   // 1,048,832
#define CAPC       160000         // per-chunk entry capacity (~70 sigma margin)

// Scratch (allocation-free __device__ globals; zero at module load, restored
// to zero by cleanup each launch so graph replays are deterministic).
__device__ int      g_pos[CAP];              // 0 = not updated, else pos+1
__device__ float    g_upd_s[BATCH * FDIM];
__device__ float    g_upd_t[BATCH * FDIM];
__device__ int      g_cnt[NCHUNK];           // per-chunk entry counts
__device__ uint64_t g_entries[NCHUNK * CAPC];// packed (src<<32)|(b*R+j)

// ---------------------------------------------------------------- update ---
__global__ void cm_update_kernel(const float* __restrict__ f_s,
                                 const float* __restrict__ f_t,
                                 const float* __restrict__ mem1,
                                 const float* __restrict__ mem2,
                                 const int*   __restrict__ s_layer_p,
                                 const int*   __restrict__ t_layer_p,
                                 const int*   __restrict__ idx)
{
    const int i     = blockIdx.x & (BATCH - 1);
    const int which = blockIdx.x >> 8;
    const int t     = threadIdx.x;

    const float* f    = which ? f_t : f_s;
    const float* mem  = which ? mem2 : mem1;
    const int layer   = which ? *t_layer_p : *s_layer_p;
    const int row     = idx[i];

    const float oldv = mem[(size_t)layer * CAP * FDIM + (size_t)row * FDIM + t];
    const float v    = 0.5f * oldv + 0.5f * f[i * FDIM + t];

    float s = v * v;
    #pragma unroll
    for (int o = 16; o; o >>= 1) s += __shfl_xor_sync(0xffffffffu, s, o);
    __shared__ float ws[4];
    if ((t & 31) == 0) ws[t >> 5] = s;
    __syncthreads();
    const float tot = ws[0] + ws[1] + ws[2] + ws[3];

    (which ? g_upd_t : g_upd_s)[i * FDIM + t] = v / sqrtf(tot);

    if (t == 0 && which == 0) g_pos[row] = i + 1;
}

// ------------------------------------------------------------------ bin ----
// One thread per (b, j) entry. Grid: (ceil(R/256), BATCH).
__global__ void cm_bin_kernel(const int* __restrict__ idx,
                              const int* __restrict__ cidx)
{
    const int j = blockIdx.x * blockDim.x + threadIdx.x;
    const int b = blockIdx.y;
    const bool valid = (j < ROWS_PER_B);

    int src = 0, chunk = 0, local = -1;
    __shared__ int s_cnt[NCHUNK], s_base[NCHUNK];
    if (threadIdx.x < NCHUNK) s_cnt[threadIdx.x] = 0;
    __syncthreads();

    if (valid) {
        src   = (j == 0) ? idx[b] : cidx[b * KNEG + (j - 1)];
        chunk = src / CHUNK_ROWS;
        if (chunk >= NCHUNK) chunk = NCHUNK - 1;
        local = atomicAdd(&s_cnt[chunk], 1);
    }
    __syncthreads();
    if (threadIdx.x < NCHUNK && s_cnt[threadIdx.x] > 0)
        s_base[threadIdx.x] = atomicAdd(&g_cnt[threadIdx.x], s_cnt[threadIdx.x]);
    __syncthreads();

    if (valid) {
        const int slot = s_base[chunk] + local;
        g_entries[chunk * CAPC + slot] =
            ((uint64_t)(uint32_t)src << 32) | (uint32_t)(b * ROWS_PER_B + j);
    }
}

// --------------------------------------------------------------- gather ----
__device__ __forceinline__ float4 ld_evict_last(const float4* p, uint64_t pol)
{
    float4 v;
    asm volatile("ld.global.L2::cache_hint.v4.f32 {%0,%1,%2,%3}, [%4], %5;"
                 : "=f"(v.x), "=f"(v.y), "=f"(v.z), "=f"(v.w)
                 : "l"(p), "l"(pol));
    return v;
}

// One warp per binned entry; copies BOTH the s-row and the t-row.
// Grid: (CAPC/8, NCHUNK) with 8 warps/block — y (chunk) is the slow
// dimension, so CTAs dispatch chunk-major and each chunk's <=64MB read set
// stays L2-resident while it is being consumed.
__global__ void cm_gather_kernel(const float* __restrict__ mem1,
                                 const float* __restrict__ mem2,
                                 const int*   __restrict__ s_layer_p,
                                 const int*   __restrict__ t_layer_p,
                                 float*       __restrict__ out)
{
    const int chunk = blockIdx.y;
    const int i     = blockIdx.x * 8 + (threadIdx.x >> 5);
    if (i >= g_cnt[chunk]) return;
    const int lane  = threadIdx.x & 31;

    const uint64_t e  = g_entries[chunk * CAPC + i];
    const int src     = (int)(e >> 32);
    const uint32_t bj = (uint32_t)e;

    uint64_t pol;
    asm("createpolicy.fractional.L2::evict_last.b64 %0, 1.0;" : "=l"(pol));

    const int p = g_pos[src];
    float4 vs, vt;
    if (p > 0) {
        vs = ((const float4*)(g_upd_s + (size_t)(p - 1) * FDIM))[lane];
        vt = ((const float4*)(g_upd_t + (size_t)(p - 1) * FDIM))[lane];
    } else {
        const size_t roff = (size_t)src * FDIM;
        vs = ld_evict_last((const float4*)(mem1 + (size_t)(*s_layer_p) * CAP * FDIM + roff) + lane, pol);
        vt = ld_evict_last((const float4*)(mem2 + (size_t)(*t_layer_p) * CAP * FDIM + roff) + lane, pol);
    }

    float4* os = (float4*)(out + (size_t)bj * FDIM);
    float4* ot = (float4*)(out + ((size_t)ENT_TOTAL + bj) * FDIM);
    __stcs(os + lane, vs);
    __stcs(ot + lane, vt);
}

// -------------------------------------------------------------- cleanup ----
__global__ void cm_cleanup_kernel(const int* __restrict__ idx)
{
    g_pos[idx[threadIdx.x]] = 0;
    if (threadIdx.x < NCHUNK) g_cnt[threadIdx.x] = 0;
}

// --------------------------------------------------------------- launch ----
extern "C" void kernel_launch(void* const* d_in, const int* in_sizes, int n_in,
                              void* d_out, int out_size)
{
    const float* f_s      = (const float*)d_in[0];
    const float* f_t      = (const float*)d_in[1];
    const float* mem1     = (const float*)d_in[2];
    const float* mem2     = (const float*)d_in[3];
    const int*   s_layer  = (const int*)  d_in[4];
    const int*   t_layer  = (const int*)  d_in[5];
    const int*   idx      = (const int*)  d_in[6];
    const int*   cidx     = (const int*)  d_in[7];
    float*       out      = (float*)d_out;

    cm_update_kernel<<<2 * BATCH, FDIM>>>(f_s, f_t, mem1, mem2, s_layer, t_layer, idx);

    dim3 bgrid((ROWS_PER_B + 255) / 256, BATCH);
    cm_bin_kernel<<<bgrid, 256>>>(idx, cidx);

    dim3 ggrid((CAPC + 7) / 8, NCHUNK);
    cm_gather_kernel<<<ggrid, 256>>>(mem1, mem2, s_layer, t_layer, out);

    cm_cleanup_kernel<<<1, BATCH>>>(idx);
}

// round 5
// speedup vs baseline: 4.5706x; 1.0607x over previous
#include <cuda_runtime.h>
#include <cstdint>

#define CAP        500000
#define FDIM       128
#define BATCH      256
#define KNEG       4096
#define ROWS_PER_B (KNEG + 1)     // 4097
#define NCHUNK     16
#define CHUNK_ROWS (CAP / NCHUNK)           // 31250 (exact)
#define ENT_TOTAL  (BATCH * ROWS_PER_B)     // 1,048,832
#define CAPC       70000          // per-chunk entry capacity (mean 65552, ~18 sigma)

// Scratch (allocation-free __device__ globals; zero at module load, restored
// to zero by cleanup each launch so graph replays are deterministic).
__device__ int      g_pos[CAP];               // 0 = not updated, else pos+1
__device__ float    g_upd_s[BATCH * FDIM];
__device__ float    g_upd_t[BATCH * FDIM];
__device__ int      g_cnt[NCHUNK];            // per-chunk entry counts
__device__ uint64_t g_entries[NCHUNK * CAPC]; // packed (src<<32)|(b*R+j)

// ----------------------------------------------------- fused update + bin --
// Blocks [0, 256): EMA + L2-normalize (block b = batch row b; threads 0-127
//   handle the s side, 128-255 the t side).
// Blocks [256, 256+4097): bin the 1,048,832 (b,j) entries by src/CHUNK_ROWS.
__global__ void cm_prep_kernel(const float* __restrict__ f_s,
                               const float* __restrict__ f_t,
                               const float* __restrict__ mem1,
                               const float* __restrict__ mem2,
                               const int*   __restrict__ s_layer_p,
                               const int*   __restrict__ t_layer_p,
                               const int*   __restrict__ idx,
                               const int*   __restrict__ cidx)
{
    if (blockIdx.x < BATCH) {
        // ---- update part ----
        const int i     = blockIdx.x;
        const int which = threadIdx.x >> 7;     // 0 = s, 1 = t
        const int t     = threadIdx.x & 127;

        const float* f     = which ? f_t : f_s;
        const float* mem   = which ? mem2 : mem1;
        const int    layer = which ? *t_layer_p : *s_layer_p;
        const int    row   = idx[i];

        const float oldv = mem[(size_t)layer * CAP * FDIM + (size_t)row * FDIM + t];
        const float v    = 0.5f * oldv + 0.5f * f[i * FDIM + t];

        float s = v * v;
        #pragma unroll
        for (int o = 16; o; o >>= 1) s += __shfl_xor_sync(0xffffffffu, s, o);
        __shared__ float ws[8];
        if ((threadIdx.x & 31) == 0) ws[threadIdx.x >> 5] = s;
        __syncthreads();
        const float tot = which ? (ws[4] + ws[5] + ws[6] + ws[7])
                                : (ws[0] + ws[1] + ws[2] + ws[3]);

        (which ? g_upd_t : g_upd_s)[i * FDIM + t] = v / sqrtf(tot);

        if (threadIdx.x == 0) g_pos[row] = i + 1;
        return;
    }

    // ---- bin part ----
    const int ent = (blockIdx.x - BATCH) * 256 + threadIdx.x;   // < 1,048,832
    const int b   = ent / ROWS_PER_B;
    const int j   = ent - b * ROWS_PER_B;

    __shared__ int s_cnt[NCHUNK], s_base[NCHUNK];
    if (threadIdx.x < NCHUNK) s_cnt[threadIdx.x] = 0;
    __syncthreads();

    const int src   = (j == 0) ? idx[b] : cidx[b * KNEG + (j - 1)];
    const int chunk = src / CHUNK_ROWS;                          // 0..15
    const int local = atomicAdd(&s_cnt[chunk], 1);
    __syncthreads();

    if (threadIdx.x < NCHUNK && s_cnt[threadIdx.x] > 0)
        s_base[threadIdx.x] = atomicAdd(&g_cnt[threadIdx.x], s_cnt[threadIdx.x]);
    __syncthreads();

    g_entries[chunk * CAPC + s_base[chunk] + local] =
        ((uint64_t)(uint32_t)src << 32) | (uint32_t)ent;
}

// --------------------------------------------------------------- gather ----
__device__ __forceinline__ float4 ld_evict_last(const float4* p, uint64_t pol)
{
    float4 v;
    asm volatile("ld.global.L2::cache_hint.v4.f32 {%0,%1,%2,%3}, [%4], %5;"
                 : "=f"(v.x), "=f"(v.y), "=f"(v.z), "=f"(v.w)
                 : "l"(p), "l"(pol));
    return v;
}

// One warp per binned entry; copies BOTH the s-row and the t-row.
// Grid: (CAPC/8, NCHUNK); y (chunk) is the slow dimension so CTAs dispatch
// chunk-major and each chunk's ~32MB read set stays L2-resident.
__global__ void cm_gather_kernel(const float* __restrict__ mem1,
                                 const float* __restrict__ mem2,
                                 const int*   __restrict__ s_layer_p,
                                 const int*   __restrict__ t_layer_p,
                                 float*       __restrict__ out)
{
    const int chunk = blockIdx.y;
    const int i     = blockIdx.x * 8 + (threadIdx.x >> 5);
    if (i >= g_cnt[chunk]) return;
    const int lane  = threadIdx.x & 31;

    const uint64_t e  = g_entries[chunk * CAPC + i];
    const int src     = (int)(e >> 32);
    const uint32_t bj = (uint32_t)e;

    uint64_t pol;
    asm("createpolicy.fractional.L2::evict_last.b64 %0, 1.0;" : "=l"(pol));

    const int p = g_pos[src];
    float4 vs, vt;
    if (p > 0) {
        vs = ((const float4*)(g_upd_s + (size_t)(p - 1) * FDIM))[lane];
        vt = ((const float4*)(g_upd_t + (size_t)(p - 1) * FDIM))[lane];
    } else {
        const size_t roff = (size_t)src * FDIM;
        vs = ld_evict_last((const float4*)(mem1 + (size_t)(*s_layer_p) * CAP * FDIM + roff) + lane, pol);
        vt = ld_evict_last((const float4*)(mem2 + (size_t)(*t_layer_p) * CAP * FDIM + roff) + lane, pol);
    }

    float4* os = (float4*)(out + (size_t)bj * FDIM);
    float4* ot = (float4*)(out + ((size_t)ENT_TOTAL + bj) * FDIM);
    __stcs(os + lane, vs);
    __stcs(ot + lane, vt);
}

// -------------------------------------------------------------- cleanup ----
__global__ void cm_cleanup_kernel(const int* __restrict__ idx)
{
    g_pos[idx[threadIdx.x]] = 0;
    if (threadIdx.x < NCHUNK) g_cnt[threadIdx.x] = 0;
}

// --------------------------------------------------------------- launch ----
extern "C" void kernel_launch(void* const* d_in, const int* in_sizes, int n_in,
                              void* d_out, int out_size)
{
    const float* f_s      = (const float*)d_in[0];
    const float* f_t      = (const float*)d_in[1];
    const float* mem1     = (const float*)d_in[2];
    const float* mem2     = (const float*)d_in[3];
    const int*   s_layer  = (const int*)  d_in[4];
    const int*   t_layer  = (const int*)  d_in[5];
    const int*   idx      = (const int*)  d_in[6];
    const int*   cidx     = (const int*)  d_in[7];
    float*       out      = (float*)d_out;

    // 256 update blocks + 4097 bin blocks (ENT_TOTAL / 256 exactly)
    cm_prep_kernel<<<BATCH + ENT_TOTAL / 256, 256>>>(f_s, f_t, mem1, mem2,
                                                     s_layer, t_layer, idx, cidx);

    dim3 ggrid((CAPC + 7) / 8, NCHUNK);
    cm_gather_kernel<<<ggrid, 256>>>(mem1, mem2, s_layer, t_layer, out);

    cm_cleanup_kernel<<<1, BATCH>>>(idx);
}